// round 5
// baseline (speedup 1.0000x reference)
#include <cuda_runtime.h>
#include <cstdint>

// ============================================================================
// CrossAttention: out = softmax((XqWq)(XkWk)^T over heads) (XvWv) Wo + bo
// N=32768 tokens, D=512, H=8  (per-token 8x8 attention across heads)
//
// Pipeline:
//   1) gemm<SPLIT=true>  : Q = queries @ Wq   [32768,4096]  (3xTF32 precision)
//   2) gemm<SPLIT=true>  : K = keys    @ Wk
//   3) gemm<SPLIT=false> : V = values  @ Wv
//   4) attn_kernel       : per-token 8x8 softmax attention  -> AO
//   5) gemm<SPLIT=false> : out = AO @ Wo + bo
// ============================================================================

#define NTOK 32768
#define DMODEL 512
#define NHEADS 8
#define DHID 4096  // NHEADS * DMODEL

// Scratch (device globals: allocation-free per harness rules). 512 MB each.
__device__ float g_Q[(size_t)NTOK * DHID];
__device__ float g_K[(size_t)NTOK * DHID];
__device__ float g_V[(size_t)NTOK * DHID];
__device__ float g_AO[(size_t)NTOK * DHID];

// ---------------------------------------------------------------------------
// helpers
// ---------------------------------------------------------------------------
__device__ __forceinline__ uint32_t f2tf32(float x) {
    uint32_t r;
    asm("cvt.rna.tf32.f32 %0, %1;" : "=r"(r) : "f"(x));
    return r;
}

__device__ __forceinline__ void mma_tf32(float* d, const uint32_t* a, const uint32_t* b) {
    asm volatile(
        "mma.sync.aligned.m16n8k8.row.col.f32.tf32.tf32.f32 "
        "{%0,%1,%2,%3}, {%4,%5,%6,%7}, {%8,%9}, {%0,%1,%2,%3};\n"
        : "+f"(d[0]), "+f"(d[1]), "+f"(d[2]), "+f"(d[3])
        : "r"(a[0]), "r"(a[1]), "r"(a[2]), "r"(a[3]),
          "r"(b[0]), "r"(b[1]));
}

__device__ __forceinline__ void cp16(uint32_t dst, const void* src) {
    asm volatile("cp.async.ca.shared.global [%0], [%1], 16;\n" :: "r"(dst), "l"(src));
}
__device__ __forceinline__ void cp_commit() { asm volatile("cp.async.commit_group;\n"); }
template<int Ng> __device__ __forceinline__ void cp_wait() {
    asm volatile("cp.async.wait_group %0;\n" :: "n"(Ng));
}

// ---------------------------------------------------------------------------
// TF32 GEMM:  C[M,N] = A[M,K] @ B[K,N] (+ bias)
// CTA tile 128x128x32, 256 threads (8 warps, 4x2), warp tile 32x64.
// SPLIT=true -> 3-pass split-tf32 (~fp32 precision) for the softmax-amplified
// Q/K path.
// ---------------------------------------------------------------------------
constexpr int BM = 128, BN = 128, BK = 32;
constexpr int APITCH = 36;   // 128x36 floats, 144B rows: conflict-free A frags
constexpr int BPITCH = 136;  // 32x136 floats, 544B rows: conflict-free B frags
constexpr int SMEM_BYTES = (2 * BM * APITCH + 2 * BK * BPITCH) * 4;  // 71680

template<bool SPLIT>
__global__ __launch_bounds__(256)
void gemm_tf32_kernel(const float* __restrict__ A, const float* __restrict__ B,
                      float* __restrict__ C, int M, int N, int K,
                      const float* __restrict__ bias)
{
    extern __shared__ float sm[];
    float* As = sm;                        // 2 * 128 * 36
    float* Bs = sm + 2 * BM * APITCH;      // 2 * 32  * 136

    const int tid = threadIdx.x;
    const int mBase = blockIdx.y * BM;
    const int nBase = blockIdx.x * BN;
    const int KT = K / BK;

    const uint32_t As_u = (uint32_t)__cvta_generic_to_shared(As);
    const uint32_t Bs_u = (uint32_t)__cvta_generic_to_shared(Bs);

    const int arow = tid >> 3, ac4 = tid & 7;    // A tile: 1024 float4, 4/thread
    const int brow = tid >> 5, bc4 = tid & 31;   // B tile: 1024 float4, 4/thread

    auto issue = [&](int kt, int buf) {
        const float* At = A + (size_t)mBase * K + (size_t)kt * BK;
        const float* Bt = B + (size_t)kt * BK * N + nBase;
        #pragma unroll
        for (int i = 0; i < 4; i++) {
            int row = arow + i * 32;
            cp16(As_u + (uint32_t)(((buf * BM + row) * APITCH + ac4 * 4) * 4),
                 At + (size_t)row * K + ac4 * 4);
        }
        #pragma unroll
        for (int i = 0; i < 4; i++) {
            int row = brow + i * 8;
            cp16(Bs_u + (uint32_t)(((buf * BK + row) * BPITCH + bc4 * 4) * 4),
                 Bt + (size_t)row * N + bc4 * 4);
        }
        cp_commit();
    };

    float acc[2][8][4];
    #pragma unroll
    for (int i = 0; i < 2; i++)
        #pragma unroll
        for (int j = 0; j < 8; j++)
            #pragma unroll
            for (int l = 0; l < 4; l++) acc[i][j][l] = 0.f;

    const int lane = tid & 31, wid = tid >> 5;
    const int g = lane >> 2, t = lane & 3;
    const int wm = (wid >> 1) * 32, wn = (wid & 1) * 64;

    issue(0, 0);

    for (int kt = 0; kt < KT; kt++) {
        const int buf = kt & 1;
        if (kt + 1 < KT) { issue(kt + 1, (kt + 1) & 1); cp_wait<1>(); }
        else             { cp_wait<0>(); }
        __syncthreads();

        const float* Ab = As + buf * BM * APITCH;
        const float* Bb = Bs + buf * BK * BPITCH;

        #pragma unroll
        for (int kk = 0; kk < BK; kk += 8) {
            uint32_t ah[2][4], al[2][4];
            #pragma unroll
            for (int mf = 0; mf < 2; mf++) {
                const int r0 = wm + mf * 16 + g;
                float x0 = Ab[r0 * APITCH + kk + t];
                float x1 = Ab[(r0 + 8) * APITCH + kk + t];
                float x2 = Ab[r0 * APITCH + kk + t + 4];
                float x3 = Ab[(r0 + 8) * APITCH + kk + t + 4];
                ah[mf][0] = f2tf32(x0); ah[mf][1] = f2tf32(x1);
                ah[mf][2] = f2tf32(x2); ah[mf][3] = f2tf32(x3);
                if (SPLIT) {
                    al[mf][0] = f2tf32(x0 - __uint_as_float(ah[mf][0]));
                    al[mf][1] = f2tf32(x1 - __uint_as_float(ah[mf][1]));
                    al[mf][2] = f2tf32(x2 - __uint_as_float(ah[mf][2]));
                    al[mf][3] = f2tf32(x3 - __uint_as_float(ah[mf][3]));
                }
            }
            #pragma unroll
            for (int nf = 0; nf < 8; nf++) {
                const int c = wn + nf * 8 + g;
                float y0 = Bb[(kk + t) * BPITCH + c];
                float y1 = Bb[(kk + t + 4) * BPITCH + c];
                uint32_t bh[2] = { f2tf32(y0), f2tf32(y1) };
                if (SPLIT) {
                    uint32_t bl[2] = { f2tf32(y0 - __uint_as_float(bh[0])),
                                       f2tf32(y1 - __uint_as_float(bh[1])) };
                    #pragma unroll
                    for (int mf = 0; mf < 2; mf++) {
                        mma_tf32(acc[mf][nf], ah[mf], bh);
                        mma_tf32(acc[mf][nf], al[mf], bh);
                        mma_tf32(acc[mf][nf], ah[mf], bl);
                    }
                } else {
                    #pragma unroll
                    for (int mf = 0; mf < 2; mf++)
                        mma_tf32(acc[mf][nf], ah[mf], bh);
                }
            }
        }
        __syncthreads();
    }

    // epilogue
    const bool hasB = (bias != nullptr);
    #pragma unroll
    for (int mf = 0; mf < 2; mf++) {
        const int row = mBase + wm + mf * 16 + g;
        #pragma unroll
        for (int nf = 0; nf < 8; nf++) {
            const int col = nBase + wn + nf * 8 + 2 * t;
            float b0 = hasB ? bias[col] : 0.f;
            float b1 = hasB ? bias[col + 1] : 0.f;
            float2 v0 = make_float2(acc[mf][nf][0] + b0, acc[mf][nf][1] + b1);
            float2 v1 = make_float2(acc[mf][nf][2] + b0, acc[mf][nf][3] + b1);
            *(float2*)&C[(size_t)row * N + col] = v0;
            *(float2*)&C[(size_t)(row + 8) * N + col] = v1;
        }
    }
}

// ---------------------------------------------------------------------------
// Per-token attention: S = Q K^T (8x8 over d=512), softmax rows, O = S V.
// One CTA (128 threads) per token; thread t owns columns {t, t+128, t+256, t+384}.
// Memory-bound: 64 KB of fp32 traffic per token.
// ---------------------------------------------------------------------------
__global__ __launch_bounds__(128)
void attn_kernel()
{
    const int n = blockIdx.x;
    const int tid = threadIdx.x;
    const size_t base = (size_t)n * DHID;

    __shared__ float red[4][64];
    __shared__ float Sf[64];
    __shared__ float P[64];

    float q[8][4], k[8][4];
    #pragma unroll
    for (int h = 0; h < 8; h++)
        #pragma unroll
        for (int j = 0; j < 4; j++) {
            const int d = tid + j * 128;
            q[h][j] = g_Q[base + h * DMODEL + d];
            k[h][j] = g_K[base + h * DMODEL + d];
        }

    float s[64];
    #pragma unroll
    for (int h = 0; h < 8; h++)
        #pragma unroll
        for (int gg = 0; gg < 8; gg++) {
            float a = 0.f;
            #pragma unroll
            for (int j = 0; j < 4; j++) a += q[h][j] * k[gg][j];
            s[h * 8 + gg] = a;
        }

    const int lane = tid & 31, w = tid >> 5;
    #pragma unroll
    for (int i = 0; i < 64; i++) {
        float v = s[i];
        v += __shfl_down_sync(0xffffffffu, v, 16);
        v += __shfl_down_sync(0xffffffffu, v, 8);
        v += __shfl_down_sync(0xffffffffu, v, 4);
        v += __shfl_down_sync(0xffffffffu, v, 2);
        v += __shfl_down_sync(0xffffffffu, v, 1);
        if (lane == 0) red[w][i] = v;
    }
    __syncthreads();
    if (tid < 64) Sf[tid] = red[0][tid] + red[1][tid] + red[2][tid] + red[3][tid];
    __syncthreads();
    if (tid < 8) {
        float m = -1e30f;
        #pragma unroll
        for (int gg = 0; gg < 8; gg++) m = fmaxf(m, Sf[tid * 8 + gg]);
        float e[8], sum = 0.f;
        #pragma unroll
        for (int gg = 0; gg < 8; gg++) { e[gg] = expf(Sf[tid * 8 + gg] - m); sum += e[gg]; }
        const float inv = 1.f / sum;
        #pragma unroll
        for (int gg = 0; gg < 8; gg++) P[tid * 8 + gg] = e[gg] * inv;
    }
    __syncthreads();

    float vv[8][4];
    #pragma unroll
    for (int h = 0; h < 8; h++)
        #pragma unroll
        for (int j = 0; j < 4; j++)
            vv[h][j] = g_V[base + h * DMODEL + tid + j * 128];

    #pragma unroll
    for (int h = 0; h < 8; h++) {
        #pragma unroll
        for (int j = 0; j < 4; j++) {
            float o = 0.f;
            #pragma unroll
            for (int gg = 0; gg < 8; gg++) o += P[h * 8 + gg] * vv[gg][j];
            g_AO[base + h * DMODEL + tid + j * 128] = o;
        }
    }
}

// ---------------------------------------------------------------------------
// launch
// ---------------------------------------------------------------------------
extern "C" void kernel_launch(void* const* d_in, const int* in_sizes, int n_in,
                              void* d_out, int out_size)
{
    const float* queries = (const float*)d_in[0];
    const float* keys    = (const float*)d_in[1];
    const float* values  = (const float*)d_in[2];
    const float* Wq      = (const float*)d_in[3];
    const float* Wk      = (const float*)d_in[4];
    const float* Wv      = (const float*)d_in[5];
    const float* Wo      = (const float*)d_in[6];
    const float* bo      = (const float*)d_in[7];
    float* out = (float*)d_out;

    float *Qp, *Kp, *Vp, *AOp;
    cudaGetSymbolAddress((void**)&Qp,  g_Q);
    cudaGetSymbolAddress((void**)&Kp,  g_K);
    cudaGetSymbolAddress((void**)&Vp,  g_V);
    cudaGetSymbolAddress((void**)&AOp, g_AO);

    cudaFuncSetAttribute(gemm_tf32_kernel<true>,
                         cudaFuncAttributeMaxDynamicSharedMemorySize, SMEM_BYTES);
    cudaFuncSetAttribute(gemm_tf32_kernel<false>,
                         cudaFuncAttributeMaxDynamicSharedMemorySize, SMEM_BYTES);

    dim3 blk(256);
    dim3 gridQKV(DHID / BN, NTOK / BM);   // 32 x 256
    dim3 gridO(DMODEL / BN, NTOK / BM);   // 4 x 256

    // Q/K projections: split-tf32 (softmax-amplified precision path)
    gemm_tf32_kernel<true><<<gridQKV, blk, SMEM_BYTES>>>(queries, Wq, Qp,
                                                         NTOK, DHID, DMODEL, nullptr);
    gemm_tf32_kernel<true><<<gridQKV, blk, SMEM_BYTES>>>(keys, Wk, Kp,
                                                         NTOK, DHID, DMODEL, nullptr);
    // V projection: single-pass tf32
    gemm_tf32_kernel<false><<<gridQKV, blk, SMEM_BYTES>>>(values, Wv, Vp,
                                                          NTOK, DHID, DMODEL, nullptr);
    // Per-token attention
    attn_kernel<<<NTOK, 128>>>();
    // Output projection + bias
    gemm_tf32_kernel<false><<<gridO, blk, SMEM_BYTES>>>(AOp, Wo, out,
                                                        NTOK, DMODEL, DHID, bo);
}

// round 8
// speedup vs baseline: 1.5325x; 1.5325x over previous
#include <cuda_runtime.h>
#include <cuda_fp16.h>
#include <cstdint>

// ============================================================================
// CrossAttention via fp16-split mma.sync GEMMs (sm_103-safe: no arch-'a' ops).
//   out = softmax((Xq Wq)(Xk Wk)^T over heads) (Xv Wv) Wo + bo
// N=32768, D=512, H=8.
//
// GEMM precision: operands pre-split to fp16 hi|lo.
//   NPASS=3 (Q,K):  Ah*Bh + Al*Bh + Ah*Bl   (~2^-22, softmax-amplified path)
//   NPASS=2 (V,O):  Ah*Bh + Al*Bh           (~2^-12, unamplified)
// ============================================================================

#define NTOK 32768
#define DMODEL 512
#define DHID 4096

// ---------------- scratch (device globals; allocation-free) -----------------
__device__ float g_Q[(size_t)NTOK * DHID];
__device__ float g_K[(size_t)NTOK * DHID];
__device__ float g_V[(size_t)NTOK * DHID];
__device__ __half g_AOs[(size_t)NTOK * 2 * DHID];     // [32768][8192] hi|lo
__device__ __half g_Xq[(size_t)NTOK * 2 * DMODEL];    // [32768][1024] hi|lo
__device__ __half g_Xk[(size_t)NTOK * 2 * DMODEL];
__device__ __half g_Xv[(size_t)NTOK * 2 * DMODEL];
__device__ __half g_Wqs[(size_t)DHID * 2 * DMODEL];   // [4096][1024] K-major hi|lo
__device__ __half g_Wks[(size_t)DHID * 2 * DMODEL];
__device__ __half g_Wvs[(size_t)DHID * 2 * DMODEL];
__device__ __half g_Wos[(size_t)DMODEL * 2 * DHID];   // [512][8192]  K-major hi|lo

// ---------------------------- PTX helpers -----------------------------------
__device__ __forceinline__ uint32_t smem_u32(const void* p) {
    uint32_t a;
    asm("{ .reg .u64 t; cvta.to.shared.u64 t, %1; cvt.u32.u64 %0, t; }" : "=r"(a) : "l"(p));
    return a;
}
#define SWZ(x) ((x) ^ (((x) >> 3) & 0x70))

__device__ __forceinline__ void cp16(uint32_t dst, const void* src) {
    asm volatile("cp.async.ca.shared.global [%0], [%1], 16;\n" :: "r"(dst), "l"(src));
}
__device__ __forceinline__ void cp_commit() { asm volatile("cp.async.commit_group;\n"); }
template<int Ng> __device__ __forceinline__ void cp_wait() {
    asm volatile("cp.async.wait_group %0;\n" :: "n"(Ng));
}

__device__ __forceinline__ void ldmx4(uint32_t* r, uint32_t addr) {
    asm volatile("ldmatrix.sync.aligned.m8n8.x4.shared.b16 {%0,%1,%2,%3}, [%4];"
                 : "=r"(r[0]), "=r"(r[1]), "=r"(r[2]), "=r"(r[3]) : "r"(addr));
}

__device__ __forceinline__ void mma_f16(float* d, const uint32_t* a, const uint32_t* b) {
    asm volatile(
        "mma.sync.aligned.m16n8k16.row.col.f32.f16.f16.f32 "
        "{%0,%1,%2,%3}, {%4,%5,%6,%7}, {%8,%9}, {%0,%1,%2,%3};\n"
        : "+f"(d[0]), "+f"(d[1]), "+f"(d[2]), "+f"(d[3])
        : "r"(a[0]), "r"(a[1]), "r"(a[2]), "r"(a[3]), "r"(b[0]), "r"(b[1]));
}

// ---------------------------------------------------------------------------
// GEMM: C[M,N] = A @ B^T (split fp16), A:[rows][lda] hi|lo (lo at +kaLo within
// row), B:[N rows][ldb] K-major hi|lo. CTA tile 128x128, BK=64 (128B SW128 rows).
// 256 threads = 8 warps (4x2), warp tile 32x64.
// ---------------------------------------------------------------------------
constexpr int TILE = 128 * 128;  // 16 KB: one 128x64 fp16 operand tile

template<int NPASS>
__global__ __launch_bounds__(256)
void gemm_split_hmma(const __half* __restrict__ A, int lda, int kaLo,
                     const __half* __restrict__ B, int ldb, int kbLo,
                     float* __restrict__ C, int ldc,
                     const float* __restrict__ bias, int KT)
{
    constexpr int STAGE = (NPASS == 3 ? 4 : 3) * TILE;  // Ah, Al, Bh[, Bl]
    extern __shared__ char smraw[];
    const uint32_t base = (smem_u32(smraw) + 1023u) & ~1023u;

    const int tid = threadIdx.x, wid = tid >> 5, lane = tid & 31;
    const int mBase = blockIdx.y * 128, nBase = blockIdx.x * 128;

    const int chunk = tid & 7;       // 16B chunk within a 128B row
    const int rbase = tid >> 3;      // 0..31

    auto issue = [&](int t, int buf) {
        const int kk = t * 64;
        const uint32_t bb = base + buf * STAGE;
        const __half* Ap = A + (size_t)mBase * lda + kk + chunk * 8;
        const __half* Bp = B + (size_t)nBase * ldb + kk + chunk * 8;
        #pragma unroll
        for (int i = 0; i < 4; i++) {
            const int row = rbase + i * 32;
            const uint32_t so = SWZ((uint32_t)(row * 128 + chunk * 16));
            cp16(bb + so,            Ap + (size_t)row * lda);          // Ah
            cp16(bb + TILE + so,     Ap + kaLo + (size_t)row * lda);   // Al
            cp16(bb + 2 * TILE + so, Bp + (size_t)row * ldb);          // Bh
            if (NPASS == 3)
                cp16(bb + 3 * TILE + so, Bp + kbLo + (size_t)row * ldb); // Bl
        }
        cp_commit();
    };

    float acc[2][8][4];
    #pragma unroll
    for (int i = 0; i < 2; i++)
        #pragma unroll
        for (int j = 0; j < 8; j++)
            #pragma unroll
            for (int l = 0; l < 4; l++) acc[i][j][l] = 0.f;

    const int g = lane >> 2, tq = lane & 3;
    const int wm = (wid >> 1) * 32, wn = (wid & 1) * 64;
    const int rowSel = lane & 15;
    const uint32_t colB = (uint32_t)((lane >> 4) * 16);  // byte offset in row

    issue(0, 0);

    for (int t = 0; t < KT; t++) {
        const int buf = t & 1;
        if (t + 1 < KT) { issue(t + 1, buf ^ 1); cp_wait<1>(); }
        else            { cp_wait<0>(); }
        __syncthreads();

        const uint32_t bb = base + buf * STAGE;
        #pragma unroll
        for (int ks = 0; ks < 4; ks++) {
            const uint32_t kbyte = (uint32_t)(ks * 32) + colB;

            uint32_t ah[2][4], al[2][4];
            #pragma unroll
            for (int mf = 0; mf < 2; mf++) {
                const uint32_t ro = (uint32_t)((wm + mf * 16 + rowSel) * 128);
                const uint32_t ad = bb + SWZ(ro + kbyte);
                ldmx4(ah[mf], ad);
                ldmx4(al[mf], ad + TILE);
            }

            uint32_t bh[8][2], bl[8][2];
            #pragma unroll
            for (int nb = 0; nb < 4; nb++) {
                const uint32_t ro = (uint32_t)((wn + nb * 16 + rowSel) * 128);
                const uint32_t ad = bb + 2 * TILE + SWZ(ro + kbyte);
                uint32_t r[4];
                ldmx4(r, ad);
                bh[nb * 2][0] = r[0]; bh[nb * 2][1] = r[2];
                bh[nb * 2 + 1][0] = r[1]; bh[nb * 2 + 1][1] = r[3];
                if (NPASS == 3) {
                    uint32_t s[4];
                    ldmx4(s, ad + TILE);
                    bl[nb * 2][0] = s[0]; bl[nb * 2][1] = s[2];
                    bl[nb * 2 + 1][0] = s[1]; bl[nb * 2 + 1][1] = s[3];
                }
            }

            #pragma unroll
            for (int mf = 0; mf < 2; mf++)
                #pragma unroll
                for (int nf = 0; nf < 8; nf++) {
                    mma_f16(acc[mf][nf], ah[mf], bh[nf]);
                    mma_f16(acc[mf][nf], al[mf], bh[nf]);
                    if (NPASS == 3) mma_f16(acc[mf][nf], ah[mf], bl[nf]);
                }
        }
        __syncthreads();
    }

    // epilogue: direct float2 stores (row g / g+8, cols 2tq..)
    const bool hasB = (bias != nullptr);
    #pragma unroll
    for (int mf = 0; mf < 2; mf++) {
        const int row = mBase + wm + mf * 16 + g;
        #pragma unroll
        for (int nf = 0; nf < 8; nf++) {
            const int col = nBase + wn + nf * 8 + 2 * tq;
            const float b0 = hasB ? bias[col] : 0.f;
            const float b1 = hasB ? bias[col + 1] : 0.f;
            *(float2*)&C[(size_t)row * ldc + col] =
                make_float2(acc[mf][nf][0] + b0, acc[mf][nf][1] + b1);
            *(float2*)&C[(size_t)(row + 8) * ldc + col] =
                make_float2(acc[mf][nf][2] + b0, acc[mf][nf][3] + b1);
        }
    }
}

// ---------------------------------------------------------------------------
// Converters
// ---------------------------------------------------------------------------
__global__ __launch_bounds__(256)
void act_split_h(const float* __restrict__ X, __half* __restrict__ Y)
{
    const int idx = blockIdx.x * 256 + threadIdx.x;  // one float4 of a 512-col row
    const int row = idx >> 7, c4 = idx & 127;
    const float4 v = ((const float4*)X)[idx];
    float f[4] = { v.x, v.y, v.z, v.w };
    __half h[4], l[4];
    #pragma unroll
    for (int i = 0; i < 4; i++) {
        h[i] = __float2half_rn(f[i]);
        l[i] = __float2half_rn(f[i] - __half2float(h[i]));
    }
    const size_t o = (size_t)row * 1024 + c4 * 4;
    __half2* ph = (__half2*)(Y + o);
    ph[0] = __halves2half2(h[0], h[1]);
    ph[1] = __halves2half2(h[2], h[3]);
    __half2* pl = (__half2*)(Y + o + DMODEL);
    pl[0] = __halves2half2(l[0], l[1]);
    pl[1] = __halves2half2(l[2], l[3]);
}

__global__ __launch_bounds__(256)
void wtrans_split_h(const float* __restrict__ W, __half* __restrict__ Y,
                    int Kin, int Nin, int ldo)
{
    __shared__ float t[32][33];
    const int n  = blockIdx.x * 32 + threadIdx.x;
    const int k0 = blockIdx.y * 32;
    #pragma unroll
    for (int i = 0; i < 4; i++)
        t[threadIdx.y + i * 8][threadIdx.x] = W[(size_t)(k0 + threadIdx.y + i * 8) * Nin + n];
    __syncthreads();
    const int kc = k0 + threadIdx.x;
    #pragma unroll
    for (int i = 0; i < 4; i++) {
        const int nr = blockIdx.x * 32 + threadIdx.y + i * 8;
        const float v = t[threadIdx.x][threadIdx.y + i * 8];
        const __half hi = __float2half_rn(v);
        const __half lo = __float2half_rn(v - __half2float(hi));
        Y[(size_t)nr * ldo + kc]       = hi;
        Y[(size_t)nr * ldo + Kin + kc] = lo;
    }
}

// ---------------------------------------------------------------------------
// Per-token attention (8x8 over heads); writes AO as split fp16 [hi|lo].
// ---------------------------------------------------------------------------
__global__ __launch_bounds__(128)
void attn_kernel()
{
    const int n = blockIdx.x;
    const int tid = threadIdx.x;
    const size_t base = (size_t)n * DHID;
    const size_t b2 = (size_t)n * (2 * DHID);

    __shared__ float red[4][64];
    __shared__ float Sf[64];
    __shared__ float P[64];

    float q[8][4], k[8][4];
    #pragma unroll
    for (int h = 0; h < 8; h++)
        #pragma unroll
        for (int j = 0; j < 4; j++) {
            const int d = tid + j * 128;
            q[h][j] = g_Q[base + h * DMODEL + d];
            k[h][j] = g_K[base + h * DMODEL + d];
        }

    float s[64];
    #pragma unroll
    for (int h = 0; h < 8; h++)
        #pragma unroll
        for (int gg = 0; gg < 8; gg++) {
            float a = 0.f;
            #pragma unroll
            for (int j = 0; j < 4; j++) a += q[h][j] * k[gg][j];
            s[h * 8 + gg] = a;
        }

    const int lane = tid & 31, w = tid >> 5;
    #pragma unroll
    for (int i = 0; i < 64; i++) {
        float v = s[i];
        v += __shfl_down_sync(0xffffffffu, v, 16);
        v += __shfl_down_sync(0xffffffffu, v, 8);
        v += __shfl_down_sync(0xffffffffu, v, 4);
        v += __shfl_down_sync(0xffffffffu, v, 2);
        v += __shfl_down_sync(0xffffffffu, v, 1);
        if (lane == 0) red[w][i] = v;
    }
    __syncthreads();
    if (tid < 64) Sf[tid] = red[0][tid] + red[1][tid] + red[2][tid] + red[3][tid];
    __syncthreads();
    if (tid < 8) {
        float m = -1e30f;
        #pragma unroll
        for (int gg = 0; gg < 8; gg++) m = fmaxf(m, Sf[tid * 8 + gg]);
        float e[8], sum = 0.f;
        #pragma unroll
        for (int gg = 0; gg < 8; gg++) { e[gg] = expf(Sf[tid * 8 + gg] - m); sum += e[gg]; }
        const float inv = 1.f / sum;
        #pragma unroll
        for (int gg = 0; gg < 8; gg++) P[tid * 8 + gg] = e[gg] * inv;
    }
    __syncthreads();

    float vv[8][4];
    #pragma unroll
    for (int h = 0; h < 8; h++)
        #pragma unroll
        for (int j = 0; j < 4; j++)
            vv[h][j] = g_V[base + h * DMODEL + tid + j * 128];

    #pragma unroll
    for (int h = 0; h < 8; h++) {
        #pragma unroll
        for (int j = 0; j < 4; j++) {
            float o = 0.f;
            #pragma unroll
            for (int gg = 0; gg < 8; gg++) o += P[h * 8 + gg] * vv[gg][j];
            const int d = h * DMODEL + tid + j * 128;
            const __half hi = __float2half_rn(o);
            const __half lo = __float2half_rn(o - __half2float(hi));
            g_AOs[b2 + d]        = hi;
            g_AOs[b2 + DHID + d] = lo;
        }
    }
}

// ---------------------------------------------------------------------------
// launch
// ---------------------------------------------------------------------------
extern "C" void kernel_launch(void* const* d_in, const int* in_sizes, int n_in,
                              void* d_out, int out_size)
{
    const float* queries = (const float*)d_in[0];
    const float* keys    = (const float*)d_in[1];
    const float* values  = (const float*)d_in[2];
    const float* Wq      = (const float*)d_in[3];
    const float* Wk      = (const float*)d_in[4];
    const float* Wv      = (const float*)d_in[5];
    const float* Wo      = (const float*)d_in[6];
    const float* bo      = (const float*)d_in[7];
    float* out = (float*)d_out;

    float *Qp, *Kp, *Vp;
    __half *Xq, *Xk, *Xv, *Wqs, *Wks, *Wvs, *Wos, *AOs;
    cudaGetSymbolAddress((void**)&Qp,  g_Q);
    cudaGetSymbolAddress((void**)&Kp,  g_K);
    cudaGetSymbolAddress((void**)&Vp,  g_V);
    cudaGetSymbolAddress((void**)&Xq,  g_Xq);
    cudaGetSymbolAddress((void**)&Xk,  g_Xk);
    cudaGetSymbolAddress((void**)&Xv,  g_Xv);
    cudaGetSymbolAddress((void**)&Wqs, g_Wqs);
    cudaGetSymbolAddress((void**)&Wks, g_Wks);
    cudaGetSymbolAddress((void**)&Wvs, g_Wvs);
    cudaGetSymbolAddress((void**)&Wos, g_Wos);
    cudaGetSymbolAddress((void**)&AOs, g_AOs);

    const int SM3 = 1024 + 2 * 4 * TILE;  // 132 KB
    const int SM2 = 1024 + 2 * 3 * TILE;  // 99 KB
    cudaFuncSetAttribute(gemm_split_hmma<3>,
                         cudaFuncAttributeMaxDynamicSharedMemorySize, SM3);
    cudaFuncSetAttribute(gemm_split_hmma<2>,
                         cudaFuncAttributeMaxDynamicSharedMemorySize, SM2);

    // 1) split converts
    act_split_h<<<16384, 256>>>(queries, Xq);
    act_split_h<<<16384, 256>>>(keys,    Xk);
    act_split_h<<<16384, 256>>>(values,  Xv);
    wtrans_split_h<<<dim3(DHID / 32, DMODEL / 32), dim3(32, 8)>>>(Wq, Wqs, DMODEL, DHID, 2 * DMODEL);
    wtrans_split_h<<<dim3(DHID / 32, DMODEL / 32), dim3(32, 8)>>>(Wk, Wks, DMODEL, DHID, 2 * DMODEL);
    wtrans_split_h<<<dim3(DHID / 32, DMODEL / 32), dim3(32, 8)>>>(Wv, Wvs, DMODEL, DHID, 2 * DMODEL);
    wtrans_split_h<<<dim3(DMODEL / 32, DHID / 32), dim3(32, 8)>>>(Wo, Wos, DHID, DMODEL, 2 * DHID);

    // 2) projections
    dim3 gProj(DHID / 128, NTOK / 128);   // (32, 256)
    gemm_split_hmma<3><<<gProj, 256, SM3>>>(Xq, 2 * DMODEL, DMODEL, Wqs, 2 * DMODEL, DMODEL,
                                            Qp, DHID, nullptr, DMODEL / 64);
    gemm_split_hmma<3><<<gProj, 256, SM3>>>(Xk, 2 * DMODEL, DMODEL, Wks, 2 * DMODEL, DMODEL,
                                            Kp, DHID, nullptr, DMODEL / 64);
    gemm_split_hmma<2><<<gProj, 256, SM2>>>(Xv, 2 * DMODEL, DMODEL, Wvs, 2 * DMODEL, DMODEL,
                                            Vp, DHID, nullptr, DMODEL / 64);

    // 3) per-token attention -> split fp16 AO
    attn_kernel<<<NTOK, 128>>>();

    // 4) output projection + bias
    dim3 gOut(DMODEL / 128, NTOK / 128);  // (4, 256)
    gemm_split_hmma<2><<<gOut, 256, SM2>>>(AOs, 2 * DHID, DHID, Wos, 2 * DHID, DHID,
                                           out, DMODEL, bo, DHID / 64);
}

// round 10
// speedup vs baseline: 1.5529x; 1.0133x over previous
#include <cuda_runtime.h>
#include <cuda_fp16.h>
#include <cstdint>

// ============================================================================
// CrossAttention via fp16-split mma.sync GEMMs (sm_103-safe: no arch-'a' ops).
//   out = softmax((Xq Wq)(Xk Wk)^T over heads) (Xv Wv) Wo + bo
// N=32768, D=512, H=8.
//
// GEMM precision: operands pre-split to fp16 hi|lo.
//   NPASS=3 (Q,K):  Ah*Bh + Al*Bh + Ah*Bl   (~2^-22, softmax-amplified path)
//   NPASS=2 (V,O):  Ah*Bh + Al*Bh           (~2^-12, unamplified)
//
// R9: CTA tile 256x128 (warp tile 64x64, 8 warps) -> halves B-side L2 traffic
//     and CTA count; cp.async.cg (L2-only).
// ============================================================================

#define NTOK 32768
#define DMODEL 512
#define DHID 4096

// ---------------- scratch (device globals; allocation-free) -----------------
__device__ float g_Q[(size_t)NTOK * DHID];
__device__ float g_K[(size_t)NTOK * DHID];
__device__ float g_V[(size_t)NTOK * DHID];
__device__ __half g_AOs[(size_t)NTOK * 2 * DHID];     // [32768][8192] hi|lo
__device__ __half g_Xq[(size_t)NTOK * 2 * DMODEL];    // [32768][1024] hi|lo
__device__ __half g_Xk[(size_t)NTOK * 2 * DMODEL];
__device__ __half g_Xv[(size_t)NTOK * 2 * DMODEL];
__device__ __half g_Wqs[(size_t)DHID * 2 * DMODEL];   // [4096][1024] K-major hi|lo
__device__ __half g_Wks[(size_t)DHID * 2 * DMODEL];
__device__ __half g_Wvs[(size_t)DHID * 2 * DMODEL];
__device__ __half g_Wos[(size_t)DMODEL * 2 * DHID];   // [512][8192]  K-major hi|lo

// ---------------------------- PTX helpers -----------------------------------
__device__ __forceinline__ uint32_t smem_u32(const void* p) {
    uint32_t a;
    asm("{ .reg .u64 t; cvta.to.shared.u64 t, %1; cvt.u32.u64 %0, t; }" : "=r"(a) : "l"(p));
    return a;
}
#define SWZ(x) ((x) ^ (((x) >> 3) & 0x70))

__device__ __forceinline__ void cp16(uint32_t dst, const void* src) {
    asm volatile("cp.async.cg.shared.global [%0], [%1], 16;\n" :: "r"(dst), "l"(src));
}
__device__ __forceinline__ void cp_commit() { asm volatile("cp.async.commit_group;\n"); }
template<int Ng> __device__ __forceinline__ void cp_wait() {
    asm volatile("cp.async.wait_group %0;\n" :: "n"(Ng));
}

__device__ __forceinline__ void ldmx4(uint32_t* r, uint32_t addr) {
    asm volatile("ldmatrix.sync.aligned.m8n8.x4.shared.b16 {%0,%1,%2,%3}, [%4];"
                 : "=r"(r[0]), "=r"(r[1]), "=r"(r[2]), "=r"(r[3]) : "r"(addr));
}

__device__ __forceinline__ void mma_f16(float* d, const uint32_t* a, const uint32_t* b) {
    asm volatile(
        "mma.sync.aligned.m16n8k16.row.col.f32.f16.f16.f32 "
        "{%0,%1,%2,%3}, {%4,%5,%6,%7}, {%8,%9}, {%0,%1,%2,%3};\n"
        : "+f"(d[0]), "+f"(d[1]), "+f"(d[2]), "+f"(d[3])
        : "r"(a[0]), "r"(a[1]), "r"(a[2]), "r"(a[3]), "r"(b[0]), "r"(b[1]));
}

// ---------------------------------------------------------------------------
// GEMM: C[M,N] = A @ B^T (split fp16), A:[rows][lda] hi|lo (lo at +kaLo within
// row), B:[N rows][ldb] K-major hi|lo. CTA tile 256x128, BK=64 (128B SW128 rows).
// 256 threads = 8 warps (4x2), warp tile 64x64.
// ---------------------------------------------------------------------------
constexpr int ATILE = 256 * 128;  // 32 KB: one 256x64 fp16 A operand tile
constexpr int BTILE = 128 * 128;  // 16 KB: one 128x64 fp16 B operand tile

template<int NPASS>
__global__ __launch_bounds__(256)
void gemm_split_hmma(const __half* __restrict__ A, int lda, int kaLo,
                     const __half* __restrict__ B, int ldb, int kbLo,
                     float* __restrict__ C, int ldc,
                     const float* __restrict__ bias, int KT)
{
    constexpr int STAGE = 2 * ATILE + (NPASS == 3 ? 2 : 1) * BTILE; // Ah,Al,Bh[,Bl]
    extern __shared__ char smraw[];
    const uint32_t base = (smem_u32(smraw) + 1023u) & ~1023u;

    const int tid = threadIdx.x, wid = tid >> 5, lane = tid & 31;
    const int mBase = blockIdx.y * 256, nBase = blockIdx.x * 128;

    const int chunk = tid & 7;       // 16B chunk within a 128B row
    const int rbase = tid >> 3;      // 0..31

    auto issue = [&](int t, int buf) {
        const int kk = t * 64;
        const uint32_t bb = base + buf * STAGE;
        const __half* Ap = A + (size_t)mBase * lda + kk + chunk * 8;
        const __half* Bp = B + (size_t)nBase * ldb + kk + chunk * 8;
        #pragma unroll
        for (int i = 0; i < 8; i++) {
            const int row = rbase + i * 32;
            const uint32_t so = SWZ((uint32_t)(row * 128 + chunk * 16));
            cp16(bb + so,         Ap + (size_t)row * lda);          // Ah
            cp16(bb + ATILE + so, Ap + kaLo + (size_t)row * lda);   // Al
        }
        #pragma unroll
        for (int i = 0; i < 4; i++) {
            const int row = rbase + i * 32;
            const uint32_t so = SWZ((uint32_t)(row * 128 + chunk * 16));
            cp16(bb + 2 * ATILE + so, Bp + (size_t)row * ldb);      // Bh
            if (NPASS == 3)
                cp16(bb + 2 * ATILE + BTILE + so, Bp + kbLo + (size_t)row * ldb); // Bl
        }
        cp_commit();
    };

    float acc[4][8][4];
    #pragma unroll
    for (int i = 0; i < 4; i++)
        #pragma unroll
        for (int j = 0; j < 8; j++)
            #pragma unroll
            for (int l = 0; l < 4; l++) acc[i][j][l] = 0.f;

    const int g = lane >> 2, tq = lane & 3;
    const int wm = (wid >> 1) * 64, wn = (wid & 1) * 64;
    const int rowSel = lane & 15;
    const uint32_t colB = (uint32_t)((lane >> 4) * 16);  // byte offset in row

    issue(0, 0);

    for (int t = 0; t < KT; t++) {
        const int buf = t & 1;
        if (t + 1 < KT) { issue(t + 1, buf ^ 1); cp_wait<1>(); }
        else            { cp_wait<0>(); }
        __syncthreads();

        const uint32_t bb = base + buf * STAGE;
        #pragma unroll
        for (int ks = 0; ks < 4; ks++) {
            const uint32_t kbyte = (uint32_t)(ks * 32) + colB;

            uint32_t ah[4][4], al[4][4];
            #pragma unroll
            for (int mf = 0; mf < 4; mf++) {
                const uint32_t ro = (uint32_t)((wm + mf * 16 + rowSel) * 128);
                const uint32_t ad = bb + SWZ(ro + kbyte);
                ldmx4(ah[mf], ad);
                ldmx4(al[mf], ad + ATILE);
            }

            uint32_t bh[8][2], bl[8][2];
            #pragma unroll
            for (int nb = 0; nb < 4; nb++) {
                const uint32_t ro = (uint32_t)((wn + nb * 16 + rowSel) * 128);
                const uint32_t ad = bb + 2 * ATILE + SWZ(ro + kbyte);
                uint32_t r[4];
                ldmx4(r, ad);
                bh[nb * 2][0] = r[0]; bh[nb * 2][1] = r[2];
                bh[nb * 2 + 1][0] = r[1]; bh[nb * 2 + 1][1] = r[3];
                if (NPASS == 3) {
                    uint32_t s[4];
                    ldmx4(s, ad + BTILE);
                    bl[nb * 2][0] = s[0]; bl[nb * 2][1] = s[2];
                    bl[nb * 2 + 1][0] = s[1]; bl[nb * 2 + 1][1] = s[3];
                }
            }

            #pragma unroll
            for (int mf = 0; mf < 4; mf++)
                #pragma unroll
                for (int nf = 0; nf < 8; nf++) {
                    mma_f16(acc[mf][nf], ah[mf], bh[nf]);
                    mma_f16(acc[mf][nf], al[mf], bh[nf]);
                    if (NPASS == 3) mma_f16(acc[mf][nf], ah[mf], bl[nf]);
                }
        }
        __syncthreads();
    }

    // epilogue: direct float2 stores (row g / g+8, cols 2tq..)
    const bool hasB = (bias != nullptr);
    #pragma unroll
    for (int mf = 0; mf < 4; mf++) {
        const int row = mBase + wm + mf * 16 + g;
        #pragma unroll
        for (int nf = 0; nf < 8; nf++) {
            const int col = nBase + wn + nf * 8 + 2 * tq;
            const float b0 = hasB ? bias[col] : 0.f;
            const float b1 = hasB ? bias[col + 1] : 0.f;
            *(float2*)&C[(size_t)row * ldc + col] =
                make_float2(acc[mf][nf][0] + b0, acc[mf][nf][1] + b1);
            *(float2*)&C[(size_t)(row + 8) * ldc + col] =
                make_float2(acc[mf][nf][2] + b0, acc[mf][nf][3] + b1);
        }
    }
}

// ---------------------------------------------------------------------------
// Converters
// ---------------------------------------------------------------------------
__global__ __launch_bounds__(256)
void act_split_h(const float* __restrict__ X, __half* __restrict__ Y)
{
    const int idx = blockIdx.x * 256 + threadIdx.x;  // one float4 of a 512-col row
    const int row = idx >> 7, c4 = idx & 127;
    const float4 v = ((const float4*)X)[idx];
    float f[4] = { v.x, v.y, v.z, v.w };
    __half h[4], l[4];
    #pragma unroll
    for (int i = 0; i < 4; i++) {
        h[i] = __float2half_rn(f[i]);
        l[i] = __float2half_rn(f[i] - __half2float(h[i]));
    }
    const size_t o = (size_t)row * 1024 + c4 * 4;
    __half2* ph = (__half2*)(Y + o);
    ph[0] = __halves2half2(h[0], h[1]);
    ph[1] = __halves2half2(h[2], h[3]);
    __half2* pl = (__half2*)(Y + o + DMODEL);
    pl[0] = __halves2half2(l[0], l[1]);
    pl[1] = __halves2half2(l[2], l[3]);
}

__global__ __launch_bounds__(256)
void wtrans_split_h(const float* __restrict__ W, __half* __restrict__ Y,
                    int Kin, int Nin, int ldo)
{
    __shared__ float t[32][33];
    const int n  = blockIdx.x * 32 + threadIdx.x;
    const int k0 = blockIdx.y * 32;
    #pragma unroll
    for (int i = 0; i < 4; i++)
        t[threadIdx.y + i * 8][threadIdx.x] = W[(size_t)(k0 + threadIdx.y + i * 8) * Nin + n];
    __syncthreads();
    const int kc = k0 + threadIdx.x;
    #pragma unroll
    for (int i = 0; i < 4; i++) {
        const int nr = blockIdx.x * 32 + threadIdx.y + i * 8;
        const float v = t[threadIdx.x][threadIdx.y + i * 8];
        const __half hi = __float2half_rn(v);
        const __half lo = __float2half_rn(v - __half2float(hi));
        Y[(size_t)nr * ldo + kc]       = hi;
        Y[(size_t)nr * ldo + Kin + kc] = lo;
    }
}

// ---------------------------------------------------------------------------
// Per-token attention (8x8 over heads); writes AO as split fp16 [hi|lo].
// ---------------------------------------------------------------------------
__global__ __launch_bounds__(128)
void attn_kernel()
{
    const int n = blockIdx.x;
    const int tid = threadIdx.x;
    const size_t base = (size_t)n * DHID;
    const size_t b2 = (size_t)n * (2 * DHID);

    __shared__ float red[4][64];
    __shared__ float Sf[64];
    __shared__ float P[64];

    float q[8][4], k[8][4];
    #pragma unroll
    for (int h = 0; h < 8; h++)
        #pragma unroll
        for (int j = 0; j < 4; j++) {
            const int d = tid + j * 128;
            q[h][j] = g_Q[base + h * DMODEL + d];
            k[h][j] = g_K[base + h * DMODEL + d];
        }

    float s[64];
    #pragma unroll
    for (int h = 0; h < 8; h++)
        #pragma unroll
        for (int gg = 0; gg < 8; gg++) {
            float a = 0.f;
            #pragma unroll
            for (int j = 0; j < 4; j++) a += q[h][j] * k[gg][j];
            s[h * 8 + gg] = a;
        }

    const int lane = tid & 31, w = tid >> 5;
    #pragma unroll
    for (int i = 0; i < 64; i++) {
        float v = s[i];
        v += __shfl_down_sync(0xffffffffu, v, 16);
        v += __shfl_down_sync(0xffffffffu, v, 8);
        v += __shfl_down_sync(0xffffffffu, v, 4);
        v += __shfl_down_sync(0xffffffffu, v, 2);
        v += __shfl_down_sync(0xffffffffu, v, 1);
        if (lane == 0) red[w][i] = v;
    }
    __syncthreads();
    if (tid < 64) Sf[tid] = red[0][tid] + red[1][tid] + red[2][tid] + red[3][tid];
    __syncthreads();
    if (tid < 8) {
        float m = -1e30f;
        #pragma unroll
        for (int gg = 0; gg < 8; gg++) m = fmaxf(m, Sf[tid * 8 + gg]);
        float e[8], sum = 0.f;
        #pragma unroll
        for (int gg = 0; gg < 8; gg++) { e[gg] = expf(Sf[tid * 8 + gg] - m); sum += e[gg]; }
        const float inv = 1.f / sum;
        #pragma unroll
        for (int gg = 0; gg < 8; gg++) P[tid * 8 + gg] = e[gg] * inv;
    }
    __syncthreads();

    float vv[8][4];
    #pragma unroll
    for (int h = 0; h < 8; h++)
        #pragma unroll
        for (int j = 0; j < 4; j++)
            vv[h][j] = g_V[base + h * DMODEL + tid + j * 128];

    #pragma unroll
    for (int h = 0; h < 8; h++) {
        #pragma unroll
        for (int j = 0; j < 4; j++) {
            float o = 0.f;
            #pragma unroll
            for (int gg = 0; gg < 8; gg++) o += P[h * 8 + gg] * vv[gg][j];
            const int d = h * DMODEL + tid + j * 128;
            const __half hi = __float2half_rn(o);
            const __half lo = __float2half_rn(o - __half2float(hi));
            g_AOs[b2 + d]        = hi;
            g_AOs[b2 + DHID + d] = lo;
        }
    }
}

// ---------------------------------------------------------------------------
// launch
// ---------------------------------------------------------------------------
extern "C" void kernel_launch(void* const* d_in, const int* in_sizes, int n_in,
                              void* d_out, int out_size)
{
    const float* queries = (const float*)d_in[0];
    const float* keys    = (const float*)d_in[1];
    const float* values  = (const float*)d_in[2];
    const float* Wq      = (const float*)d_in[3];
    const float* Wk      = (const float*)d_in[4];
    const float* Wv      = (const float*)d_in[5];
    const float* Wo      = (const float*)d_in[6];
    const float* bo      = (const float*)d_in[7];
    float* out = (float*)d_out;

    float *Qp, *Kp, *Vp;
    __half *Xq, *Xk, *Xv, *Wqs, *Wks, *Wvs, *Wos, *AOs;
    cudaGetSymbolAddress((void**)&Qp,  g_Q);
    cudaGetSymbolAddress((void**)&Kp,  g_K);
    cudaGetSymbolAddress((void**)&Vp,  g_V);
    cudaGetSymbolAddress((void**)&Xq,  g_Xq);
    cudaGetSymbolAddress((void**)&Xk,  g_Xk);
    cudaGetSymbolAddress((void**)&Xv,  g_Xv);
    cudaGetSymbolAddress((void**)&Wqs, g_Wqs);
    cudaGetSymbolAddress((void**)&Wks, g_Wks);
    cudaGetSymbolAddress((void**)&Wvs, g_Wvs);
    cudaGetSymbolAddress((void**)&Wos, g_Wos);
    cudaGetSymbolAddress((void**)&AOs, g_AOs);

    const int SM3 = 1024 + 2 * (2 * ATILE + 2 * BTILE);  // ~193 KB
    const int SM2 = 1024 + 2 * (2 * ATILE + 1 * BTILE);  // ~161 KB
    cudaFuncSetAttribute(gemm_split_hmma<3>,
                         cudaFuncAttributeMaxDynamicSharedMemorySize, SM3);
    cudaFuncSetAttribute(gemm_split_hmma<2>,
                         cudaFuncAttributeMaxDynamicSharedMemorySize, SM2);

    // 1) split converts
    act_split_h<<<16384, 256>>>(queries, Xq);
    act_split_h<<<16384, 256>>>(keys,    Xk);
    act_split_h<<<16384, 256>>>(values,  Xv);
    wtrans_split_h<<<dim3(DHID / 32, DMODEL / 32), dim3(32, 8)>>>(Wq, Wqs, DMODEL, DHID, 2 * DMODEL);
    wtrans_split_h<<<dim3(DHID / 32, DMODEL / 32), dim3(32, 8)>>>(Wk, Wks, DMODEL, DHID, 2 * DMODEL);
    wtrans_split_h<<<dim3(DHID / 32, DMODEL / 32), dim3(32, 8)>>>(Wv, Wvs, DMODEL, DHID, 2 * DMODEL);
    wtrans_split_h<<<dim3(DMODEL / 32, DHID / 32), dim3(32, 8)>>>(Wo, Wos, DHID, DMODEL, 2 * DHID);

    // 2) projections
    dim3 gProj(DHID / 128, NTOK / 256);   // (32, 128)
    gemm_split_hmma<3><<<gProj, 256, SM3>>>(Xq, 2 * DMODEL, DMODEL, Wqs, 2 * DMODEL, DMODEL,
                                            Qp, DHID, nullptr, DMODEL / 64);
    gemm_split_hmma<3><<<gProj, 256, SM3>>>(Xk, 2 * DMODEL, DMODEL, Wks, 2 * DMODEL, DMODEL,
                                            Kp, DHID, nullptr, DMODEL / 64);
    gemm_split_hmma<2><<<gProj, 256, SM2>>>(Xv, 2 * DMODEL, DMODEL, Wvs, 2 * DMODEL, DMODEL,
                                            Vp, DHID, nullptr, DMODEL / 64);

    // 3) per-token attention -> split fp16 AO
    attn_kernel<<<NTOK, 128>>>();

    // 4) output projection + bias
    dim3 gOut(DMODEL / 128, NTOK / 256);  // (4, 128)
    gemm_split_hmma<2><<<gOut, 256, SM2>>>(AOs, 2 * DHID, DHID, Wos, 2 * DHID, DHID,
                                           out, DMODEL, bo, DHID / 64);
}